// round 9
// baseline (speedup 1.0000x reference)
#include <cuda_runtime.h>
#include <cstdint>

// Problem constants
#define BSZ   4
#define CSQ   1024
#define PSQ   1024
#define DIN   1024
#define NH    16
#define HDIM  64
#define TT    2048        // T = CS + PS
#define LQG   4096        // BSZ*CSQ global query rows
#define HD    1024        // NH*HDIM
#define SCALE 0.125f      // 1/sqrt(64)

// ---------------------------------------------------------------------------
// Scratch (device globals; no dynamic allocation allowed)
// ---------------------------------------------------------------------------
__device__ float g_q [(size_t)LQG * HD];                 //  16.8 MB  q_tfmd
__device__ float g_kv[(size_t)BSZ * TT * 2 * HD];        //  67 MB    [k | v]
__device__ float g_p [(size_t)TT * HD];                  //   8.4 MB  p_tfmd
__device__ float g_P [(size_t)NH * LQG * TT];            // 512 MB    (q+v)@p^T per head
__device__ float g_ao[(size_t)LQG * HD];                 //  16.8 MB  attn output (pre W_out)

// ---------------------------------------------------------------------------
// tf32 / mma / cp.async helpers
// ---------------------------------------------------------------------------
__device__ __forceinline__ float tf32r(float x) {
    float y;
    asm("cvt.rna.tf32.f32 %0, %1;" : "=f"(y) : "f"(x));
    return y;
}
__device__ __forceinline__ float4 tf32r4(float4 v) {
    return make_float4(tf32r(v.x), tf32r(v.y), tf32r(v.z), tf32r(v.w));
}

// D += A(16x8 row) * B(8x8 col)
__device__ __forceinline__ void mma8(float* d, const float* a, const float* b) {
    asm volatile(
        "mma.sync.aligned.m16n8k8.row.col.f32.tf32.tf32.f32 "
        "{%0,%1,%2,%3}, {%4,%5,%6,%7}, {%8,%9}, {%0,%1,%2,%3};"
        : "+f"(d[0]), "+f"(d[1]), "+f"(d[2]), "+f"(d[3])
        : "r"(__float_as_uint(a[0])), "r"(__float_as_uint(a[1])),
          "r"(__float_as_uint(a[2])), "r"(__float_as_uint(a[3])),
          "r"(__float_as_uint(b[0])), "r"(__float_as_uint(b[1])));
}

__device__ __forceinline__ uint32_t smem_u32(const void* p) {
    return (uint32_t)__cvta_generic_to_shared(p);
}
#define CPA16(dst, src) \
    asm volatile("cp.async.cg.shared.global [%0], [%1], 16;" :: "r"(dst), "l"(src))
#define CPA_COMMIT() asm volatile("cp.async.commit_group;")
#define CPA_WAIT(n)  asm volatile("cp.async.wait_group %0;" :: "n"(n))
#define CPA_WAIT_TAIL(rem) do {                         \
        if ((rem) >= 2)      CPA_WAIT(2);               \
        else if ((rem) == 1) CPA_WAIT(1);               \
        else                 CPA_WAIT(0);               \
    } while (0)

// ---------------------------------------------------------------------------
// Generic 128x128 tf32 GEMM, row-major A(MxK) * B(KxN) -> C(MxN), K%16==0,
// K>=64. MODE 0: A plain. MODE 1: A rows = virtual concat(memory, input_).
// 128 threads = 4 warps 2(m)x2(n); warp tile 64x64 = 4x8 m16n8 tiles.
// 4-stage cp.async pipeline; A staged [row][k] pitch 20 (conflict-free),
// B staged [k][n] pitch 136. tf32 cvt at fragment-load time (same numerics).
// Dynamic SMEM: 4*(128*20 + 16*136)*4 = 75776 B.
// ---------------------------------------------------------------------------
#define GEMM_SMEM ((4 * (128 * 20) + 4 * (16 * 136)) * 4)

template <int MODE>
__global__ void __launch_bounds__(128) gemm_tf32(
    const float* __restrict__ A, const float* __restrict__ A2,
    const float* __restrict__ B, float* __restrict__ C,
    int M, int N, int K)
{
    extern __shared__ float sm[];
    float (*As)[128][20] = reinterpret_cast<float(*)[128][20]>(sm);
    float (*Bs)[16][136] = reinterpret_cast<float(*)[16][136]>(sm + 4 * 128 * 20);

    const int tid  = threadIdx.x;
    const int lane = tid & 31;
    const int w    = tid >> 5;
    const int wm   = (w >> 1) * 64;
    const int wn   = (w & 1) * 64;
    const int bm   = blockIdx.y * 128;
    const int bn   = blockIdx.x * 128;
    const int ms   = lane >> 2;
    const int kb   = lane & 3;

    const float* arow;
    if (MODE == 0) {
        arow = A + (size_t)(bm + tid) * K;
    } else {
        int row = bm + tid;
        int b   = row / TT;
        int r   = row - b * TT;
        arow = (r < PSQ) ? A  + (size_t)(b * PSQ + r)         * K
                         : A2 + (size_t)(b * CSQ + (r - PSQ)) * K;
    }

    auto issue = [&](int s, int k0) {
        uint32_t ad = smem_u32(&As[s][tid][0]);
        CPA16(ad,      arow + k0);
        CPA16(ad + 16, arow + k0 + 4);
        CPA16(ad + 32, arow + k0 + 8);
        CPA16(ad + 48, arow + k0 + 12);
#pragma unroll
        for (int i = 0; i < 4; i++) {
            int id = tid + 128 * i;
            int kR = id >> 5;
            int ch = id & 31;
            CPA16(smem_u32(&Bs[s][kR][ch * 4]),
                  B + (size_t)(k0 + kR) * N + bn + ch * 4);
        }
        CPA_COMMIT();
    };

    const int T = K / 16;
    issue(0, 0); issue(1, 16); issue(2, 32);

    float acc[4][8][4] = {};

    for (int t = 0; t < T; t++) {
        CPA_WAIT_TAIL(T - 1 - t);
        __syncthreads();
        if (t + 3 < T) issue((t + 3) & 3, (t + 3) * 16);
        const int s = t & 3;
#pragma unroll
        for (int kk = 0; kk < 16; kk += 8) {
            const int kr = kk + kb;
            float a[4][4], b[8][2];
#pragma unroll
            for (int mt = 0; mt < 4; mt++) {
                a[mt][0] = tf32r(As[s][wm + mt * 16 + ms][kr]);
                a[mt][1] = tf32r(As[s][wm + mt * 16 + ms + 8][kr]);
                a[mt][2] = tf32r(As[s][wm + mt * 16 + ms][kr + 4]);
                a[mt][3] = tf32r(As[s][wm + mt * 16 + ms + 8][kr + 4]);
            }
#pragma unroll
            for (int nt = 0; nt < 8; nt++) {
                b[nt][0] = tf32r(Bs[s][kr][wn + nt * 8 + ms]);
                b[nt][1] = tf32r(Bs[s][kr + 4][wn + nt * 8 + ms]);
            }
#pragma unroll
            for (int mt = 0; mt < 4; mt++)
#pragma unroll
                for (int nt = 0; nt < 8; nt++)
                    mma8(acc[mt][nt], a[mt], b[nt]);
        }
    }

#pragma unroll
    for (int mt = 0; mt < 4; mt++) {
        int r0 = bm + wm + mt * 16 + ms;
#pragma unroll
        for (int nt = 0; nt < 8; nt++) {
            int c0 = bn + wn + nt * 8 + kb * 2;
            *(float2*)&C[(size_t)r0 * N + c0]       = make_float2(acc[mt][nt][0], acc[mt][nt][1]);
            *(float2*)&C[(size_t)(r0 + 8) * N + c0] = make_float2(acc[mt][nt][2], acc[mt][nt][3]);
        }
    }
}

// ---------------------------------------------------------------------------
// P[h][L][jj] = sum_d (q[L,h,d]+v[h,d]) * p[jj,h,d]   (NT, K=64)
// 4-stage cp.async; both tiles staged [row][k] pitch 20; v added at
// fragment-load time from preloaded registers (same rounding as before).
// Dynamic SMEM: 2 * 4*128*20*4 = 81920 B.
// ---------------------------------------------------------------------------
#define POS_SMEM (2 * 4 * 128 * 20 * 4)

__global__ void __launch_bounds__(128) pos_gemm_tf32(
    const float* __restrict__ q, const float* __restrict__ p,
    const float* __restrict__ vb, float* __restrict__ P)
{
    extern __shared__ float sm[];
    float (*As)[128][20] = reinterpret_cast<float(*)[128][20]>(sm);
    float (*Bs)[128][20] = reinterpret_cast<float(*)[128][20]>(sm + 4 * 128 * 20);

    const int tid  = threadIdx.x;
    const int lane = tid & 31;
    const int w    = tid >> 5;
    const int wm   = (w >> 1) * 64;
    const int wn   = (w & 1) * 64;
    const int h    = blockIdx.z;
    const int L0   = blockIdx.y * 128;
    const int j0   = blockIdx.x * 128;
    const int ms   = lane >> 2;
    const int kb   = lane & 3;

    const float* arow = q + (size_t)(L0 + tid) * HD + h * HDIM;
    const float* brow = p + (size_t)(j0 + tid) * HD + h * HDIM;

    // v bias values this lane needs: per k-tile t, kk in {0,8}: k = 16t+kk+kb (+4)
    float vv[4][4];
#pragma unroll
    for (int t = 0; t < 4; t++) {
        vv[t][0] = vb[h * HDIM + 16 * t + kb];
        vv[t][1] = vb[h * HDIM + 16 * t + kb + 4];
        vv[t][2] = vb[h * HDIM + 16 * t + 8 + kb];
        vv[t][3] = vb[h * HDIM + 16 * t + 8 + kb + 4];
    }

    auto issue = [&](int s, int k0) {
        uint32_t ad = smem_u32(&As[s][tid][0]);
        CPA16(ad,      arow + k0);
        CPA16(ad + 16, arow + k0 + 4);
        CPA16(ad + 32, arow + k0 + 8);
        CPA16(ad + 48, arow + k0 + 12);
        uint32_t bd = smem_u32(&Bs[s][tid][0]);
        CPA16(bd,      brow + k0);
        CPA16(bd + 16, brow + k0 + 4);
        CPA16(bd + 32, brow + k0 + 8);
        CPA16(bd + 48, brow + k0 + 12);
        CPA_COMMIT();
    };

    const int T = 4;   // HDIM / 16
    issue(0, 0); issue(1, 16); issue(2, 32);

    float acc[4][8][4] = {};

#pragma unroll
    for (int t = 0; t < T; t++) {
        CPA_WAIT_TAIL(T - 1 - t);
        __syncthreads();
        if (t + 3 < T) issue((t + 3) & 3, (t + 3) * 16);
        const int s = t & 3;
#pragma unroll
        for (int kk = 0; kk < 16; kk += 8) {
            const int kr  = kk + kb;
            const float vk  = (kk == 0) ? vv[t][0] : vv[t][2];
            const float vk4 = (kk == 0) ? vv[t][1] : vv[t][3];
            float a[4][4], b[8][2];
#pragma unroll
            for (int mt = 0; mt < 4; mt++) {
                a[mt][0] = tf32r(As[s][wm + mt * 16 + ms][kr]     + vk);
                a[mt][1] = tf32r(As[s][wm + mt * 16 + ms + 8][kr] + vk);
                a[mt][2] = tf32r(As[s][wm + mt * 16 + ms][kr + 4]     + vk4);
                a[mt][3] = tf32r(As[s][wm + mt * 16 + ms + 8][kr + 4] + vk4);
            }
#pragma unroll
            for (int nt = 0; nt < 8; nt++) {
                b[nt][0] = tf32r(Bs[s][wn + nt * 8 + ms][kr]);
                b[nt][1] = tf32r(Bs[s][wn + nt * 8 + ms][kr + 4]);
            }
#pragma unroll
            for (int mt = 0; mt < 4; mt++)
#pragma unroll
                for (int nt = 0; nt < 8; nt++)
                    mma8(acc[mt][nt], a[mt], b[nt]);
        }
    }

#pragma unroll
    for (int mt = 0; mt < 4; mt++) {
        int r0 = L0 + wm + mt * 16 + ms;
#pragma unroll
        for (int nt = 0; nt < 8; nt++) {
            int c0 = j0 + wn + nt * 8 + kb * 2;
            float* o = P + ((size_t)h * LQG + r0) * TT + c0;
            *(float2*)o            = make_float2(acc[mt][nt][0], acc[mt][nt][1]);
            *(float2*)(o + 8 * TT) = make_float2(acc[mt][nt][2], acc[mt][nt][3]);
        }
    }
}

// ---------------------------------------------------------------------------
// rel_shift gather: pos(b,i,j) with L = b*CS+i
// ---------------------------------------------------------------------------
__device__ __forceinline__ float pos_val(const float* __restrict__ Pm,
                                         int h, int L, int jj)
{
    int s  = jj + LQG - L;
    int n  = (s > TT) + (s > 2 * TT + 1);
    int jp = s - n * (TT + 1);
    int Lp = L + n;
    float pos = 0.f;
    if (jp > 0 && Lp < LQG)
        pos = Pm[((size_t)h * LQG + Lp) * TT + (jp - 1)];
    return pos;
}

// ---------------------------------------------------------------------------
// Fused attention: scores (+pos gather, mask, scale) -> online softmax -> P@V.
// (Unchanged from the passing R8 kernel.)
// ---------------------------------------------------------------------------
#define ATT_SMEM ((64 * 136 + 64 * 72 + 64 * 72) * 4)

__global__ void __launch_bounds__(256) attn_fused(
    const float* __restrict__ q, const float* __restrict__ kv,
    const float* __restrict__ ub, const float* __restrict__ Pm,
    float* __restrict__ ao)
{
    extern __shared__ float dyn[];
    float (*Sp)[136] = (float(*)[136])dyn;
    float (*Bk)[72]  = (float(*)[72])(dyn + 64 * 136);
    float (*Bv)[72]  = (float(*)[72])(dyn + 64 * 136 + 64 * 72);

    const int tid  = threadIdx.x;
    const int lane = tid & 31;
    const int w    = tid >> 5;
    const int wm   = w * 16;
    const int bh   = blockIdx.y;
    const int b    = bh >> 4;
    const int h    = bh & 15;
    const int i0   = blockIdx.x * 128;
    const int r    = lane >> 2;
    const int kb   = lane & 3;

    {
        int row = tid >> 1;
        int kq  = (tid & 1) * 32;
        const float* qr = q  + (size_t)(b * CSQ + i0 + row) * HD + h * HDIM + kq;
        const float* ur = ub + h * HDIM + kq;
#pragma unroll
        for (int i = 0; i < 8; i++) {
            float4 a  = *(const float4*)(qr + i * 4);
            float4 uu = *(const float4*)(ur + i * 4);
            Sp[kq + i * 4 + 0][row] = tf32r(a.x + uu.x);
            Sp[kq + i * 4 + 1][row] = tf32r(a.y + uu.y);
            Sp[kq + i * 4 + 2][row] = tf32r(a.z + uu.z);
            Sp[kq + i * 4 + 3][row] = tf32r(a.w + uu.w);
        }
    }
    __syncthreads();
    float aq[8][4];
#pragma unroll
    for (int ks = 0; ks < 8; ks++) {
        aq[ks][0] = Sp[ks * 8 + kb][wm + r];
        aq[ks][1] = Sp[ks * 8 + kb][wm + r + 8];
        aq[ks][2] = Sp[ks * 8 + kb + 4][wm + r];
        aq[ks][3] = Sp[ks * 8 + kb + 4][wm + r + 8];
    }
    __syncthreads();

    float m0 = -3.0e38f, m1 = -3.0e38f, l0 = 0.f, l1 = 0.f;
    float acc_o[8][4] = {};

    const int row0 = i0 + wm + r;
    const int Lr   = b * CSQ + row0;
    const int Kef  = min(TT, i0 + 128 + PSQ);

    for (int j0 = 0; j0 < Kef; j0 += 64) {
        {
            int j  = tid & 63;
            int dq = (tid >> 6) * 16;
            const float* kr_ = kv + ((size_t)(b * TT + j0 + j)) * (2 * HD) + h * HDIM + dq;
#pragma unroll
            for (int i = 0; i < 4; i++) {
                float4 kx = *(const float4*)(kr_ + i * 4);
                Bk[dq + i * 4 + 0][j] = tf32r(kx.x);
                Bk[dq + i * 4 + 1][j] = tf32r(kx.y);
                Bk[dq + i * 4 + 2][j] = tf32r(kx.z);
                Bk[dq + i * 4 + 3][j] = tf32r(kx.w);
            }
            const float* vr_ = kr_ + HD;
#pragma unroll
            for (int i = 0; i < 4; i++) {
                float4 vx = *(const float4*)(vr_ + i * 4);
                *(float4*)&Bv[j][dq + i * 4] = tf32r4(vx);
            }
        }
        __syncthreads();

        float s[8][4] = {};
#pragma unroll
        for (int ks = 0; ks < 8; ks++) {
            float bq[8][2];
#pragma unroll
            for (int nt = 0; nt < 8; nt++) {
                bq[nt][0] = Bk[ks * 8 + kb][nt * 8 + r];
                bq[nt][1] = Bk[ks * 8 + kb + 4][nt * 8 + r];
            }
#pragma unroll
            for (int nt = 0; nt < 8; nt++)
                mma8(s[nt], aq[ks], bq[nt]);
        }

#pragma unroll
        for (int nt = 0; nt < 8; nt++) {
            int jjb = j0 + nt * 8 + 2 * kb;
#pragma unroll
            for (int cc = 0; cc < 2; cc++) {
                int jj = jjb + cc;
                s[nt][cc]     = (jj > row0 + PSQ)     ? -1e30f
                              : (s[nt][cc]     + pos_val(Pm, h, Lr, jj))     * SCALE;
                s[nt][2 + cc] = (jj > row0 + 8 + PSQ) ? -1e30f
                              : (s[nt][2 + cc] + pos_val(Pm, h, Lr + 8, jj)) * SCALE;
            }
        }

        float tm0 = -3.0e38f, tm1 = -3.0e38f;
#pragma unroll
        for (int nt = 0; nt < 8; nt++) {
            tm0 = fmaxf(tm0, fmaxf(s[nt][0], s[nt][1]));
            tm1 = fmaxf(tm1, fmaxf(s[nt][2], s[nt][3]));
        }
        tm0 = fmaxf(tm0, __shfl_xor_sync(0xffffffffu, tm0, 1));
        tm0 = fmaxf(tm0, __shfl_xor_sync(0xffffffffu, tm0, 2));
        tm1 = fmaxf(tm1, __shfl_xor_sync(0xffffffffu, tm1, 1));
        tm1 = fmaxf(tm1, __shfl_xor_sync(0xffffffffu, tm1, 2));
        float mn0 = fmaxf(m0, tm0), mn1 = fmaxf(m1, tm1);
        float f0 = __expf(m0 - mn0), f1 = __expf(m1 - mn1);

        float ps0 = 0.f, ps1 = 0.f;
#pragma unroll
        for (int nt = 0; nt < 8; nt++) {
            s[nt][0] = __expf(s[nt][0] - mn0);
            s[nt][1] = __expf(s[nt][1] - mn0);
            s[nt][2] = __expf(s[nt][2] - mn1);
            s[nt][3] = __expf(s[nt][3] - mn1);
            ps0 += s[nt][0] + s[nt][1];
            ps1 += s[nt][2] + s[nt][3];
        }
        ps0 += __shfl_xor_sync(0xffffffffu, ps0, 1);
        ps0 += __shfl_xor_sync(0xffffffffu, ps0, 2);
        ps1 += __shfl_xor_sync(0xffffffffu, ps1, 1);
        ps1 += __shfl_xor_sync(0xffffffffu, ps1, 2);
        l0 = l0 * f0 + ps0;
        l1 = l1 * f1 + ps1;
        m0 = mn0; m1 = mn1;

#pragma unroll
        for (int nt = 0; nt < 8; nt++) {
            acc_o[nt][0] *= f0; acc_o[nt][1] *= f0;
            acc_o[nt][2] *= f1; acc_o[nt][3] *= f1;
        }

#pragma unroll
        for (int nt = 0; nt < 8; nt++) {
            int jl = nt * 8 + 2 * kb;
            Sp[jl    ][wm + r]     = tf32r(s[nt][0]);
            Sp[jl + 1][wm + r]     = tf32r(s[nt][1]);
            Sp[jl    ][wm + r + 8] = tf32r(s[nt][2]);
            Sp[jl + 1][wm + r + 8] = tf32r(s[nt][3]);
        }
        __syncwarp();

#pragma unroll
        for (int kj = 0; kj < 8; kj++) {
            float a[4];
            a[0] = Sp[kj * 8 + kb][wm + r];
            a[1] = Sp[kj * 8 + kb][wm + r + 8];
            a[2] = Sp[kj * 8 + kb + 4][wm + r];
            a[3] = Sp[kj * 8 + kb + 4][wm + r + 8];
            float bq[8][2];
#pragma unroll
            for (int nt = 0; nt < 8; nt++) {
                bq[nt][0] = Bv[kj * 8 + kb][nt * 8 + r];
                bq[nt][1] = Bv[kj * 8 + kb + 4][nt * 8 + r];
            }
#pragma unroll
            for (int nt = 0; nt < 8; nt++)
                mma8(acc_o[nt], a, bq[nt]);
        }
        __syncthreads();
    }

    float inv0 = 1.0f / l0, inv1 = 1.0f / l1;
#pragma unroll
    for (int nt = 0; nt < 8; nt++) {
        int c0 = nt * 8 + 2 * kb;
        float* o0 = ao + (size_t)(b * CSQ + row0) * HD + h * HDIM + c0;
        *(float2*)o0            = make_float2(acc_o[nt][0] * inv0, acc_o[nt][1] * inv0);
        *(float2*)(o0 + 8 * HD) = make_float2(acc_o[nt][2] * inv1, acc_o[nt][3] * inv1);
    }
}

// ---------------------------------------------------------------------------
// Launch: 6 kernels, default stream, graph-capturable.
// Inputs: input_, pos_embs, memory, u, v, W_kv, W_q, W_p, W_out, mask(unused).
// ---------------------------------------------------------------------------
extern "C" void kernel_launch(void* const* d_in, const int* in_sizes, int n_in,
                              void* d_out, int out_size)
{
    const float* input_ = (const float*)d_in[0];
    const float* pos    = (const float*)d_in[1];
    const float* memory = (const float*)d_in[2];
    const float* u      = (const float*)d_in[3];
    const float* v      = (const float*)d_in[4];
    const float* W_kv   = (const float*)d_in[5];
    const float* W_q    = (const float*)d_in[6];
    const float* W_p    = (const float*)d_in[7];
    const float* W_out  = (const float*)d_in[8];
    float* out = (float*)d_out;

    float *qb, *kvb, *pb, *Pb, *aob;
    cudaGetSymbolAddress((void**)&qb,  g_q);
    cudaGetSymbolAddress((void**)&kvb, g_kv);
    cudaGetSymbolAddress((void**)&pb,  g_p);
    cudaGetSymbolAddress((void**)&Pb,  g_P);
    cudaGetSymbolAddress((void**)&aob, g_ao);

    cudaFuncSetAttribute(gemm_tf32<0>,
                         cudaFuncAttributeMaxDynamicSharedMemorySize, GEMM_SMEM);
    cudaFuncSetAttribute(gemm_tf32<1>,
                         cudaFuncAttributeMaxDynamicSharedMemorySize, GEMM_SMEM);
    cudaFuncSetAttribute(pos_gemm_tf32,
                         cudaFuncAttributeMaxDynamicSharedMemorySize, POS_SMEM);
    cudaFuncSetAttribute(attn_fused,
                         cudaFuncAttributeMaxDynamicSharedMemorySize, ATT_SMEM);

    dim3 thr(128);

    // q = input_ @ W_q                      (4096 x 1024 x 1024)
    gemm_tf32<0><<<dim3(HD / 128, LQG / 128), thr, GEMM_SMEM>>>(input_, nullptr, W_q, qb, LQG, HD, DIN);
    // kv = concat(memory, input_) @ W_kv    (8192 x 2048 x 1024)
    gemm_tf32<1><<<dim3(2 * HD / 128, (BSZ * TT) / 128), thr, GEMM_SMEM>>>(memory, input_, W_kv, kvb, BSZ * TT, 2 * HD, DIN);
    // p = pos_embs @ W_p                    (2048 x 1024 x 1024)
    gemm_tf32<0><<<dim3(HD / 128, TT / 128), thr, GEMM_SMEM>>>(pos, nullptr, W_p, pb, TT, HD, DIN);
    // P[h] = (q + v) @ p^T per head         (16 x 4096 x 2048 x 64)
    pos_gemm_tf32<<<dim3(TT / 128, LQG / 128, NH), thr, POS_SMEM>>>(qb, pb, v, Pb);
    // fused: scores + rel-shift + mask + online softmax + attn@V
    attn_fused<<<dim3(CSQ / 128, BSZ * NH), 256, ATT_SMEM>>>(qb, kvb, u, Pb, aob);
    // out = ao @ W_out                      (4096 x 1024 x 1024)
    gemm_tf32<0><<<dim3(DIN / 128, LQG / 128), thr, GEMM_SMEM>>>(aob, nullptr, W_out, out, LQG, DIN, HD);
}